// round 6
// baseline (speedup 1.0000x reference)
#include <cuda_runtime.h>
#include <cstdint>

#define H 256
#define DD 64
#define NB_PRE 128          // Gram blocks in k_pre (+1 setup block)
#define NB_MAIN 128         // blocks in k_main (2 output neurons each)

// ---------------- persistent device state (no allocations) ----------------
__device__ float g_h1[H], g_h2[H], g_h3[H], g_h4[H], g_s[H];
__device__ float g_gd[4][H];     // g', g'', g''', g'''' at a_n
__device__ float g_G[H * H];     // Gram: G[m,t] = sum_i W1[m,i] W1[t,i]
__device__ double g_accum = 0.0;
__device__ unsigned int g_done = 0;

// ---------------- kernel 1: setup (1 block) + Gram (128 blocks) ----------------
__global__ __launch_bounds__(256) void k_pre(
    const float* __restrict__ x,  const float* __restrict__ W1,
    const float* __restrict__ b1, const float* __restrict__ W2,
    const float* __restrict__ b2)
{
    int tid = threadIdx.x;
    if (blockIdx.x == NB_PRE) {
        // ---- forward pass + tanh derivative chains ----
        __shared__ float sx[DD];
        __shared__ float sh[H];
        if (tid < DD) sx[tid] = x[tid];
        __syncthreads();

        int m = tid;
        float z = b1[m], s = 0.f;
        const float4* wr = (const float4*)(W1 + m * DD);
#pragma unroll
        for (int i = 0; i < DD / 4; i++) {
            float4 w = wr[i];
            float4 xv = *(const float4*)(sx + 4 * i);
            z += w.x * xv.x + w.y * xv.y + w.z * xv.z + w.w * xv.w;
            s += w.x * w.x + w.y * w.y + w.z * w.z + w.w * w.w;
        }
        float h = tanhf(z), w = 1.f - h * h;
        g_h1[m] = w;
        g_h2[m] = -2.f * h * w;
        g_h3[m] = (4.f * h * h - 2.f * w) * w;
        g_h4[m] = (16.f * w - 8.f * h * h) * h * w;
        g_s[m] = s;
        sh[m] = h;
        __syncthreads();

        int n = tid;
        float a = b2[n];
        const float4* w2r = (const float4*)(W2 + n * H);
#pragma unroll 8
        for (int i = 0; i < H / 4; i++) {
            float4 wv = __ldg(w2r + i);
            a += wv.x * sh[4 * i] + wv.y * sh[4 * i + 1] +
                 wv.z * sh[4 * i + 2] + wv.w * sh[4 * i + 3];
        }
        float g = tanhf(a), gw = 1.f - g * g;
        g_gd[0][n] = gw;
        g_gd[1][n] = -2.f * g * gw;
        g_gd[2][n] = (4.f * g * g - 2.f * gw) * gw;
        g_gd[3][n] = (16.f * gw - 8.f * g * g) * g * gw;
    } else {
        // ---- Gram rows m0, m0+1 ----
        __shared__ float srow[2][DD];
        int m0 = 2 * blockIdx.x;
        if (tid < 2 * DD) srow[tid >> 6][tid & 63] = W1[(m0 + (tid >> 6)) * DD + (tid & 63)];
        __syncthreads();

        int t = tid;
        const float4* myr = (const float4*)(W1 + t * DD);
        float a0 = 0.f, a1 = 0.f;
#pragma unroll
        for (int i = 0; i < DD / 4; i++) {
            float4 v = __ldg(myr + i);
            a0 += srow[0][4*i]*v.x + srow[0][4*i+1]*v.y + srow[0][4*i+2]*v.z + srow[0][4*i+3]*v.w;
            a1 += srow[1][4*i]*v.x + srow[1][4*i+1]*v.y + srow[1][4*i+2]*v.z + srow[1][4*i+3]*v.w;
        }
        g_G[(m0 + 0) * H + t] = a0;
        g_G[(m0 + 1) * H + t] = a1;
    }
}

// ---------------- kernel 2: contractions, K-split across warps ----------------
//   M[n,t] = sum_m (W2[n,m] h1_m) G[m,t]
//   P[n,t] = sum_m (W2[n,m] h2_m) G[m,t]^2
//   Q = <A,M>, R = <B,M^2>, Z = <B,P>, U = <W2 h3 s, M>, L = <B,s>, Y = <W2 h4 s^2, 1>
//   contrib_n = W3[n] * ( g4 Q^2 + g3 (2LQ + 4R) + g2 (L^2 + 2Z + 4U) + g1 Y )
__global__ __launch_bounds__(256) void k_main(
    const float* __restrict__ W2, const float* __restrict__ W3,
    float* __restrict__ out)
{
    __shared__ float4 sAB[H];                 // {A0, A1, B0, B1} per m (4KB)
    __shared__ float sU0[H], sU1[H];          // 2KB
    __shared__ float pM0s[8][H], pM1s[8][H];  // 16KB
    __shared__ float pP0s[8][H], pP1s[8][H];  // 16KB
    __shared__ float sred[8][12];

    int tid = threadIdx.x;
    int wid = tid >> 5, lane = tid & 31;
    int n0 = 2 * blockIdx.x;

    float pL0, pL1, pY0, pY1;
    {
        int m = tid;
        float w20 = __ldg(&W2[n0 * H + m]);
        float w21 = __ldg(&W2[(n0 + 1) * H + m]);
        float h1 = g_h1[m], h2 = g_h2[m], h3 = g_h3[m], h4 = g_h4[m], s = g_s[m];
        float A0 = w20 * h1, A1 = w21 * h1;
        float B0 = w20 * h2, B1 = w21 * h2;
        sAB[m] = make_float4(A0, A1, B0, B1);
        sU0[m] = w20 * h3 * s;
        sU1[m] = w21 * h3 * s;
        pL0 = B0 * s;  pL1 = B1 * s;
        pY0 = w20 * h4 * s * s;
        pY1 = w21 * h4 * s * s;
    }
    __syncthreads();

    // ---- phase 1: warp w sums m in [32w, 32w+32); lane covers t = lane+32k ----
    float M0[8], M1[8], P0[8], P1[8];
#pragma unroll
    for (int k = 0; k < 8; k++) { M0[k] = M1[k] = P0[k] = P1[k] = 0.f; }

    const float* Gbase = g_G + (wid * 32) * H + lane;
#pragma unroll 2
    for (int m = 0; m < 32; m++) {
        float gv[8];
#pragma unroll
        for (int k = 0; k < 8; k++) gv[k] = __ldg(Gbase + m * H + 32 * k);
        float4 ab = sAB[wid * 32 + m];
#pragma unroll
        for (int k = 0; k < 8; k++) {
            float g2 = gv[k] * gv[k];
            M0[k] += ab.x * gv[k];
            M1[k] += ab.y * gv[k];
            P0[k] += ab.z * g2;
            P1[k] += ab.w * g2;
        }
    }
#pragma unroll
    for (int k = 0; k < 8; k++) {
        int t = lane + 32 * k;
        pM0s[wid][t] = M0[k];
        pM1s[wid][t] = M1[k];
        pP0s[wid][t] = P0[k];
        pP1s[wid][t] = P1[k];
    }
    __syncthreads();

    // ---- phase 2: combine partials; thread owns t = tid ----
    float m0 = 0.f, m1 = 0.f, q0 = 0.f, q1 = 0.f;
#pragma unroll
    for (int w = 0; w < 8; w++) {
        m0 += pM0s[w][tid];
        m1 += pM1s[w][tid];
        q0 += pP0s[w][tid];
        q1 += pP1s[w][tid];
    }

    // per-thread partials (12 scalars: 2 n x {Q,R,Z,U,L,Y})
    float4 ab = sAB[tid];
    float p[12];
    p[0]  = ab.x * m0;        p[1]  = ab.z * m0 * m0;  p[2]  = ab.z * q0;
    p[3]  = sU0[tid] * m0;    p[4]  = pL0;             p[5]  = pY0;
    p[6]  = ab.y * m1;        p[7]  = ab.w * m1 * m1;  p[8]  = ab.w * q1;
    p[9]  = sU1[tid] * m1;    p[10] = pL1;             p[11] = pY1;

#pragma unroll
    for (int k = 0; k < 12; k++) {
        float v = p[k];
#pragma unroll
        for (int s = 16; s > 0; s >>= 1) v += __shfl_down_sync(0xFFFFFFFFu, v, s);
        p[k] = v;
    }
    if (lane == 0) {
#pragma unroll
        for (int k = 0; k < 12; k++) sred[wid][k] = p[k];
    }
    __syncthreads();

    if (tid == 0) {
        double dsum = 0.0;
#pragma unroll
        for (int nn = 0; nn < 2; nn++) {
            float Q = 0.f, R = 0.f, Z = 0.f, U = 0.f, L = 0.f, Y = 0.f;
#pragma unroll
            for (int w = 0; w < 8; w++) {
                Q += sred[w][nn * 6 + 0];
                R += sred[w][nn * 6 + 1];
                Z += sred[w][nn * 6 + 2];
                U += sred[w][nn * 6 + 3];
                L += sred[w][nn * 6 + 4];
                Y += sred[w][nn * 6 + 5];
            }
            int n = n0 + nn;
            float g1 = g_gd[0][n], g2 = g_gd[1][n], g3 = g_gd[2][n], g4 = g_gd[3][n];
            float val = g4 * Q * Q
                      + g3 * (2.f * L * Q + 4.f * R)
                      + g2 * (L * L + 2.f * Z + 4.f * U)
                      + g1 * Y;
            dsum += (double)(__ldg(&W3[n]) * val);
        }
        atomicAdd(&g_accum, dsum);
        __threadfence();
        unsigned int old = atomicAdd(&g_done, 1u);
        if (old == NB_MAIN - 1) {
            double r = atomicAdd(&g_accum, 0.0);
            out[0] = (float)r;
            g_accum = 0.0;
            g_done = 0u;
            __threadfence();
        }
    }
}

// ---------------- launch ----------------
extern "C" void kernel_launch(void* const* d_in, const int* in_sizes, int n_in,
                              void* d_out, int out_size) {
    const float* x  = (const float*)d_in[0];
    const float* W1 = (const float*)d_in[1];
    const float* b1 = (const float*)d_in[2];
    const float* W2 = (const float*)d_in[3];
    const float* b2 = (const float*)d_in[4];
    const float* W3 = (const float*)d_in[5];
    // d_in[6] = b3: does not affect the 4th derivative
    float* out = (float*)d_out;

    k_pre<<<NB_PRE + 1, 256>>>(x, W1, b1, W2, b2);
    k_main<<<NB_MAIN, 256>>>(W2, W3, out);
}

// round 7
// speedup vs baseline: 1.5863x; 1.5863x over previous
#include <cuda_runtime.h>
#include <cstdint>

#define H 256
#define DD 64
#define NB_MAIN 128         // blocks in k_main (2 output neurons each)

// ---------------- persistent device state (no allocations) ----------------
__device__ float g_G[H * H];     // Gram: G[m,t] = sum_i W1[m,i] W1[t,i]
__device__ double g_accum = 0.0;
__device__ unsigned int g_done = 0;

// ---------------- kernel 1: Gram matrix only (128 blocks, 2 rows each) ----------------
__global__ __launch_bounds__(256) void k_pre(const float* __restrict__ W1)
{
    __shared__ float srow[2][DD];
    int tid = threadIdx.x;
    int m0 = 2 * blockIdx.x;
    if (tid < 2 * DD) srow[tid >> 6][tid & 63] = W1[(m0 + (tid >> 6)) * DD + (tid & 63)];
    __syncthreads();

    int t = tid;
    const float4* myr = (const float4*)(W1 + t * DD);
    float a0 = 0.f, a1 = 0.f;
#pragma unroll
    for (int i = 0; i < DD / 4; i++) {
        float4 v = __ldg(myr + i);
        a0 += srow[0][4*i]*v.x + srow[0][4*i+1]*v.y + srow[0][4*i+2]*v.z + srow[0][4*i+3]*v.w;
        a1 += srow[1][4*i]*v.x + srow[1][4*i+1]*v.y + srow[1][4*i+2]*v.z + srow[1][4*i+3]*v.w;
    }
    g_G[(m0 + 0) * H + t] = a0;
    g_G[(m0 + 1) * H + t] = a1;
}

// ---------------- kernel 2: fused setup + contractions ----------------
// Per block (output neurons n0, n0+1):
//  phase 0: x -> smem; per-thread (m=tid) layer-1 forward, tanh chains h1..h4,
//           row norms s; A/B/U coefficient vectors; warps 0-1 compute
//           a_n = W2 h + b2 and the g'..g'''' chain.
//  phase 1: double-buffered smem staging of G (8 chunks x 32 rows); inner loop
//           accumulates M[n,t], P[n,t] per thread t from smem.
//  phase 2: contraction Q,R,Z,U,L,Y; block reduce; final formula; one atomic.
__global__ __launch_bounds__(256) void k_main(
    const float* __restrict__ x,  const float* __restrict__ W1,
    const float* __restrict__ b1, const float* __restrict__ W2,
    const float* __restrict__ b2, const float* __restrict__ W3,
    float* __restrict__ out)
{
    extern __shared__ float sm[];
    float*  sG  = sm;                    // 2 x 32 x 256 = 16384 floats (64KB)
    float4* sAB = (float4*)(sm + 16384); // 256 float4 (4KB)
    float*  sU0 = sm + 16384 + 1024;     // 256
    float*  sU1 = sU0 + 256;             // 256
    float*  sh  = sU1 + 256;             // 256
    float*  sx  = sh + 256;              // 64
    float*  sgd = sx + 64;               // 8: g1..g4 for n0, n1
    float*  sred = sgd + 8;              // 8 x 12

    int tid = threadIdx.x;
    int wid = tid >> 5, lane = tid & 31;
    int n0 = 2 * blockIdx.x;

    // ---- phase 0: setup ----
    if (tid < DD) sx[tid] = x[tid];
    __syncthreads();

    float pL0, pL1, pY0, pY1;
    {
        int m = tid;
        float z = b1[m], s = 0.f;
        const float4* wr = (const float4*)(W1 + m * DD);
#pragma unroll
        for (int i = 0; i < DD / 4; i++) {
            float4 w = __ldg(wr + i);
            float4 xv = *(const float4*)(sx + 4 * i);
            z += w.x * xv.x + w.y * xv.y + w.z * xv.z + w.w * xv.w;
            s += w.x * w.x + w.y * w.y + w.z * w.z + w.w * w.w;
        }
        float h = tanhf(z), w = 1.f - h * h;
        float h1 = w;
        float h2 = -2.f * h * w;
        float h3 = (4.f * h * h - 2.f * w) * w;
        float h4 = (16.f * w - 8.f * h * h) * h * w;
        float w20 = __ldg(&W2[n0 * H + m]);
        float w21 = __ldg(&W2[(n0 + 1) * H + m]);
        float A0 = w20 * h1, A1 = w21 * h1;
        float B0 = w20 * h2, B1 = w21 * h2;
        sAB[m] = make_float4(A0, A1, B0, B1);
        sU0[m] = w20 * h3 * s;
        sU1[m] = w21 * h3 * s;
        pL0 = B0 * s;  pL1 = B1 * s;
        pY0 = w20 * h4 * s * s;
        pY1 = w21 * h4 * s * s;
        sh[m] = h;
    }
    __syncthreads();

    // warps 0,1: a_n = W2[n] . h + b2[n]  ->  g derivative chain into sgd
    if (wid < 2) {
        int n = n0 + wid;
        float a = 0.f;
#pragma unroll
        for (int k = 0; k < 8; k++) {
            int m = lane + 32 * k;
            a += __ldg(&W2[n * H + m]) * sh[m];
        }
#pragma unroll
        for (int s = 16; s > 0; s >>= 1) a += __shfl_down_sync(0xFFFFFFFFu, a, s);
        if (lane == 0) {
            a += b2[n];
            float g = tanhf(a), gw = 1.f - g * g;
            sgd[wid * 4 + 0] = gw;
            sgd[wid * 4 + 1] = -2.f * g * gw;
            sgd[wid * 4 + 2] = (4.f * g * g - 2.f * gw) * gw;
            sgd[wid * 4 + 3] = (16.f * gw - 8.f * g * g) * g * gw;
        }
    }

    // ---- phase 1: double-buffered G staging + accumulation ----
    float M0 = 0.f, M1 = 0.f, P0 = 0.f, P1 = 0.f;
    float4 gnext[8];

    // preload chunk 0
#pragma unroll
    for (int i = 0; i < 8; i++) {
        int flat = i * 256 + tid;          // float4 index within 32x256 chunk
        gnext[i] = __ldg((const float4*)g_G + flat);
    }
#pragma unroll
    for (int i = 0; i < 8; i++) {
        int flat = i * 256 + tid;
        *(float4*)(sG + 4 * flat) = gnext[i];
    }
    __syncthreads();

#pragma unroll 1
    for (int c = 0; c < 8; c++) {
        int buf = c & 1;
        // issue loads for next chunk
        if (c < 7) {
#pragma unroll
            for (int i = 0; i < 8; i++) {
                int flat = i * 256 + tid;
                gnext[i] = __ldg((const float4*)g_G + (c + 1) * 2048 + flat);
            }
        }
        // compute from current buffer (covers load latency)
        const float* gb = sG + buf * 8192;
        const float4* abb = sAB + c * 32;
#pragma unroll
        for (int mm = 0; mm < 32; mm++) {
            float g = gb[mm * 256 + tid];
            float4 ab = abb[mm];
            float gg = g * g;
            M0 += ab.x * g;
            M1 += ab.y * g;
            P0 += ab.z * gg;
            P1 += ab.w * gg;
        }
        // store next chunk into the other buffer
        if (c < 7) {
            float* gdst = sG + (buf ^ 1) * 8192;
#pragma unroll
            for (int i = 0; i < 8; i++) {
                int flat = i * 256 + tid;
                *(float4*)(gdst + 4 * flat) = gnext[i];
            }
        }
        __syncthreads();
    }

    // ---- phase 2: contraction ----
    float4 ab = sAB[tid];
    float p[12];
    p[0]  = ab.x * M0;        p[1]  = ab.z * M0 * M0;  p[2]  = ab.z * P0;
    p[3]  = sU0[tid] * M0;    p[4]  = pL0;             p[5]  = pY0;
    p[6]  = ab.y * M1;        p[7]  = ab.w * M1 * M1;  p[8]  = ab.w * P1;
    p[9]  = sU1[tid] * M1;    p[10] = pL1;             p[11] = pY1;

#pragma unroll
    for (int k = 0; k < 12; k++) {
        float v = p[k];
#pragma unroll
        for (int s = 16; s > 0; s >>= 1) v += __shfl_down_sync(0xFFFFFFFFu, v, s);
        p[k] = v;
    }
    if (lane == 0) {
#pragma unroll
        for (int k = 0; k < 12; k++) sred[wid * 12 + k] = p[k];
    }
    __syncthreads();

    if (tid == 0) {
        double dsum = 0.0;
#pragma unroll
        for (int nn = 0; nn < 2; nn++) {
            float Q = 0.f, R = 0.f, Z = 0.f, U = 0.f, L = 0.f, Y = 0.f;
#pragma unroll
            for (int w = 0; w < 8; w++) {
                Q += sred[w * 12 + nn * 6 + 0];
                R += sred[w * 12 + nn * 6 + 1];
                Z += sred[w * 12 + nn * 6 + 2];
                U += sred[w * 12 + nn * 6 + 3];
                L += sred[w * 12 + nn * 6 + 4];
                Y += sred[w * 12 + nn * 6 + 5];
            }
            float g1 = sgd[nn * 4 + 0], g2 = sgd[nn * 4 + 1];
            float g3 = sgd[nn * 4 + 2], g4 = sgd[nn * 4 + 3];
            float val = g4 * Q * Q
                      + g3 * (2.f * L * Q + 4.f * R)
                      + g2 * (L * L + 2.f * Z + 4.f * U)
                      + g1 * Y;
            dsum += (double)(__ldg(&W3[n0 + nn]) * val);
        }
        atomicAdd(&g_accum, dsum);
        __threadfence();
        unsigned int old = atomicAdd(&g_done, 1u);
        if (old == NB_MAIN - 1) {
            double r = atomicAdd(&g_accum, 0.0);
            out[0] = (float)r;
            g_accum = 0.0;
            g_done = 0u;
            __threadfence();
        }
    }
}

// ---------------- launch ----------------
extern "C" void kernel_launch(void* const* d_in, const int* in_sizes, int n_in,
                              void* d_out, int out_size) {
    const float* x  = (const float*)d_in[0];
    const float* W1 = (const float*)d_in[1];
    const float* b1 = (const float*)d_in[2];
    const float* W2 = (const float*)d_in[3];
    const float* b2 = (const float*)d_in[4];
    const float* W3 = (const float*)d_in[5];
    // d_in[6] = b3: does not affect the 4th derivative
    float* out = (float*)d_out;

    const int smem = (16384 + 1024 + 256 + 256 + 256 + 64 + 8 + 96) * 4 + 256;
    cudaFuncSetAttribute(k_main, cudaFuncAttributeMaxDynamicSharedMemorySize, smem);

    k_pre<<<NB_MAIN, 256>>>(W1);
    k_main<<<NB_MAIN, 256, smem>>>(x, W1, b1, W2, b2, W3, out);
}

// round 8
// speedup vs baseline: 1.7492x; 1.1027x over previous
#include <cuda_runtime.h>
#include <cstdint>

#define H 256
#define DD 64
#define NB_MAIN 128         // blocks in k_main (2 output neurons each)

// ---------------- persistent device state (no allocations) ----------------
__device__ float g_G[H * H];     // Gram: G[m,t] = sum_i W1[m,i] W1[t,i]
__device__ double g_accum = 0.0;
__device__ unsigned int g_done = 0;

// ---------------- kernel 1: Gram matrix (128 blocks, 2 rows each) ----------------
__global__ __launch_bounds__(256) void k_pre(const float* __restrict__ W1)
{
    __shared__ float srow[2][DD];
    int tid = threadIdx.x;
    int m0 = 2 * blockIdx.x;
    if (tid < 2 * DD) srow[tid >> 6][tid & 63] = W1[(m0 + (tid >> 6)) * DD + (tid & 63)];
    __syncthreads();

    int t = tid;
    const float4* myr = (const float4*)(W1 + t * DD);
    float a0 = 0.f, a1 = 0.f;
#pragma unroll
    for (int i = 0; i < DD / 4; i++) {
        float4 v = __ldg(myr + i);
        a0 += srow[0][4*i]*v.x + srow[0][4*i+1]*v.y + srow[0][4*i+2]*v.z + srow[0][4*i+3]*v.w;
        a1 += srow[1][4*i]*v.x + srow[1][4*i+1]*v.y + srow[1][4*i+2]*v.z + srow[1][4*i+3]*v.w;
    }
    g_G[(m0 + 0) * H + t] = a0;
    g_G[(m0 + 1) * H + t] = a1;
}

// ---------------- kernel 2: fused setup + contractions, 512 threads ----------------
// Block = output neurons (n0, n0+1). Group g = tid>>8 sums m in [128g, 128g+128)
// with its own double-buffered smem staging of G (4 chunks x 32 rows) and its own
// named barrier. Partial M/P combined through smem; contraction by threads 0-255.
__global__ __launch_bounds__(512) void k_main(
    const float* __restrict__ x,  const float* __restrict__ W1,
    const float* __restrict__ b1, const float* __restrict__ W2,
    const float* __restrict__ b2, const float* __restrict__ W3,
    float* __restrict__ out)
{
    extern __shared__ float sm[];
    float*  sG    = sm;                          // 2 grp x 2 buf x 8192 = 32768 floats
    float4* sPart = (float4*)(sm + 32768);       // 512 float4 = 2048 floats
    float4* sAB   = (float4*)(sm + 32768 + 2048);// 256 float4 = 1024 floats
    float*  sU0   = sm + 32768 + 2048 + 1024;    // 256
    float*  sU1   = sU0 + 256;                   // 256
    float*  sh    = sU1 + 256;                   // 256
    float*  sx    = sh + 256;                    // 64
    float*  sgd   = sx + 64;                     // 8
    float*  sred  = sgd + 8;                     // 96

    int tid = threadIdx.x;
    int grp = tid >> 8;          // 0 or 1
    int t   = tid & 255;
    int wid = tid >> 5, lane = tid & 31;
    int n0 = 2 * blockIdx.x;

    // ---- phase 0: setup (threads 0-255) ----
    if (tid < DD) sx[tid] = x[tid];
    __syncthreads();

    float pL0 = 0.f, pL1 = 0.f, pY0 = 0.f, pY1 = 0.f;
    if (tid < H) {
        int m = tid;
        float z = b1[m], s = 0.f;
        const float4* wr = (const float4*)(W1 + m * DD);
#pragma unroll
        for (int i = 0; i < DD / 4; i++) {
            float4 w = __ldg(wr + i);
            float4 xv = *(const float4*)(sx + 4 * i);
            z += w.x * xv.x + w.y * xv.y + w.z * xv.z + w.w * xv.w;
            s += w.x * w.x + w.y * w.y + w.z * w.z + w.w * w.w;
        }
        float h = tanhf(z), w = 1.f - h * h;
        float h1 = w;
        float h2 = -2.f * h * w;
        float h3 = (4.f * h * h - 2.f * w) * w;
        float h4 = (16.f * w - 8.f * h * h) * h * w;
        float w20 = __ldg(&W2[n0 * H + m]);
        float w21 = __ldg(&W2[(n0 + 1) * H + m]);
        float A0 = w20 * h1, A1 = w21 * h1;
        float B0 = w20 * h2, B1 = w21 * h2;
        sAB[m] = make_float4(A0, A1, B0, B1);
        sU0[m] = w20 * h3 * s;
        sU1[m] = w21 * h3 * s;
        pL0 = B0 * s;  pL1 = B1 * s;
        pY0 = w20 * h4 * s * s;
        pY1 = w21 * h4 * s * s;
        sh[m] = h;
    }
    __syncthreads();

    // warps 0,1: a_n = W2[n].h + b2[n] -> g'..g'''' into sgd
    if (wid < 2) {
        int n = n0 + wid;
        float a = 0.f;
#pragma unroll
        for (int k = 0; k < 8; k++) {
            int m = lane + 32 * k;
            a += __ldg(&W2[n * H + m]) * sh[m];
        }
#pragma unroll
        for (int s = 16; s > 0; s >>= 1) a += __shfl_down_sync(0xFFFFFFFFu, a, s);
        if (lane == 0) {
            a += b2[n];
            float g = tanhf(a), gw = 1.f - g * g;
            sgd[wid * 4 + 0] = gw;
            sgd[wid * 4 + 1] = -2.f * g * gw;
            sgd[wid * 4 + 2] = (4.f * g * g - 2.f * gw) * gw;
            sgd[wid * 4 + 3] = (16.f * gw - 8.f * g * g) * g * gw;
        }
    }

    // ---- phase 1: per-group double-buffered G staging + accumulation ----
    float M0 = 0.f, M1 = 0.f, P0 = 0.f, P1 = 0.f;
    float* myG = sG + grp * 16384;      // this group's two 8192-float buffers
    int mbase = grp * 128;
    int barid = 1 + grp;

    const float4* Gv = (const float4*)g_G;
    float4 gnext[8];

    // preload chunk 0 of this group's m-range
#pragma unroll
    for (int i = 0; i < 8; i++) gnext[i] = __ldg(Gv + mbase * 64 + i * 256 + t);
#pragma unroll
    for (int i = 0; i < 8; i++) *(float4*)(myG + 4 * (i * 256 + t)) = gnext[i];
    asm volatile("bar.sync %0, 256;" :: "r"(barid) : "memory");

#pragma unroll 1
    for (int c = 0; c < 4; c++) {
        if (c < 3) {
#pragma unroll
            for (int i = 0; i < 8; i++)
                gnext[i] = __ldg(Gv + (mbase + (c + 1) * 32) * 64 + i * 256 + t);
        }
        const float* gb = myG + (c & 1) * 8192;
        const float4* abb = sAB + mbase + c * 32;
#pragma unroll
        for (int mm = 0; mm < 32; mm++) {
            float g = gb[mm * 256 + t];
            float4 ab = abb[mm];
            float gg = g * g;
            M0 += ab.x * g;
            M1 += ab.y * g;
            P0 += ab.z * gg;
            P1 += ab.w * gg;
        }
        if (c < 3) {
            float* gdst = myG + ((c + 1) & 1) * 8192;
#pragma unroll
            for (int i = 0; i < 8; i++)
                *(float4*)(gdst + 4 * (i * 256 + t)) = gnext[i];
        }
        asm volatile("bar.sync %0, 256;" :: "r"(barid) : "memory");
    }

    sPart[tid] = make_float4(M0, M1, P0, P1);
    __syncthreads();

    // ---- phase 2: combine group partials + contraction (threads 0-255) ----
    if (tid < H) {
        float4 a = sPart[t], b = sPart[256 + t];
        float m0 = a.x + b.x, m1 = a.y + b.y;
        float q0 = a.z + b.z, q1 = a.w + b.w;

        float4 ab = sAB[t];
        float p[12];
        p[0]  = ab.x * m0;      p[1]  = ab.z * m0 * m0;  p[2]  = ab.z * q0;
        p[3]  = sU0[t] * m0;    p[4]  = pL0;             p[5]  = pY0;
        p[6]  = ab.y * m1;      p[7]  = ab.w * m1 * m1;  p[8]  = ab.w * q1;
        p[9]  = sU1[t] * m1;    p[10] = pL1;             p[11] = pY1;

#pragma unroll
        for (int k = 0; k < 12; k++) {
            float v = p[k];
#pragma unroll
            for (int s = 16; s > 0; s >>= 1) v += __shfl_down_sync(0xFFFFFFFFu, v, s);
            p[k] = v;
        }
        if (lane == 0) {
#pragma unroll
            for (int k = 0; k < 12; k++) sred[wid * 12 + k] = p[k];
        }
    }
    __syncthreads();

    if (tid == 0) {
        double dsum = 0.0;
#pragma unroll
        for (int nn = 0; nn < 2; nn++) {
            float Q = 0.f, R = 0.f, Z = 0.f, U = 0.f, L = 0.f, Y = 0.f;
#pragma unroll
            for (int w = 0; w < 8; w++) {
                Q += sred[w * 12 + nn * 6 + 0];
                R += sred[w * 12 + nn * 6 + 1];
                Z += sred[w * 12 + nn * 6 + 2];
                U += sred[w * 12 + nn * 6 + 3];
                L += sred[w * 12 + nn * 6 + 4];
                Y += sred[w * 12 + nn * 6 + 5];
            }
            float g1 = sgd[nn * 4 + 0], g2 = sgd[nn * 4 + 1];
            float g3 = sgd[nn * 4 + 2], g4 = sgd[nn * 4 + 3];
            float val = g4 * Q * Q
                      + g3 * (2.f * L * Q + 4.f * R)
                      + g2 * (L * L + 2.f * Z + 4.f * U)
                      + g1 * Y;
            dsum += (double)(__ldg(&W3[n0 + nn]) * val);
        }
        atomicAdd(&g_accum, dsum);
        __threadfence();
        unsigned int old = atomicAdd(&g_done, 1u);
        if (old == NB_MAIN - 1) {
            double r = atomicAdd(&g_accum, 0.0);
            out[0] = (float)r;
            g_accum = 0.0;
            g_done = 0u;
            __threadfence();
        }
    }
}

// ---------------- launch ----------------
extern "C" void kernel_launch(void* const* d_in, const int* in_sizes, int n_in,
                              void* d_out, int out_size) {
    const float* x  = (const float*)d_in[0];
    const float* W1 = (const float*)d_in[1];
    const float* b1 = (const float*)d_in[2];
    const float* W2 = (const float*)d_in[3];
    const float* b2 = (const float*)d_in[4];
    const float* W3 = (const float*)d_in[5];
    // d_in[6] = b3: does not affect the 4th derivative
    float* out = (float*)d_out;

    const int smem = (32768 + 2048 + 1024 + 256 + 256 + 256 + 64 + 8 + 96) * 4;
    cudaFuncSetAttribute(k_main, cudaFuncAttributeMaxDynamicSharedMemorySize, smem);

    k_pre<<<NB_MAIN, 256>>>(W1);
    k_main<<<NB_MAIN, 512, smem>>>(x, W1, b1, W2, b2, W3, out);
}

// round 9
// speedup vs baseline: 1.9678x; 1.1250x over previous
#include <cuda_runtime.h>
#include <cstdint>

#define H 256
#define DD 64
#define NB_MAIN 128         // blocks in k_main (2 output neurons each)

// ---------------- persistent device state (no allocations) ----------------
__device__ float g_G[H * H];     // Gram: G[m,t] = sum_i W1[m,i] W1[t,i]
__device__ double g_accum = 0.0;
__device__ unsigned int g_done = 0;

// ---------------- kernel 1: Gram matrix (128 blocks, 2 rows each) ----------------
__global__ __launch_bounds__(256) void k_pre(const float* __restrict__ W1)
{
    __shared__ float srow[2][DD];
    int tid = threadIdx.x;
    int m0 = 2 * blockIdx.x;
    if (tid < 2 * DD) srow[tid >> 6][tid & 63] = W1[(m0 + (tid >> 6)) * DD + (tid & 63)];
    __syncthreads();

    int t = tid;
    const float4* myr = (const float4*)(W1 + t * DD);
    float a0 = 0.f, a1 = 0.f;
#pragma unroll
    for (int i = 0; i < DD / 4; i++) {
        float4 v = __ldg(myr + i);
        a0 += srow[0][4*i]*v.x + srow[0][4*i+1]*v.y + srow[0][4*i+2]*v.z + srow[0][4*i+3]*v.w;
        a1 += srow[1][4*i]*v.x + srow[1][4*i+1]*v.y + srow[1][4*i+2]*v.z + srow[1][4*i+3]*v.w;
    }
    g_G[(m0 + 0) * H + t] = a0;
    g_G[(m0 + 1) * H + t] = a1;
}

// ---------------- kernel 2: fused setup + contractions, 512 threads ----------------
// Block = output neurons (n0, n0+1). Thread = (ms = tid>>6, ts = tid&63):
// owns t-columns 4*ts..4*ts+3 and m-slice [32*ms, 32*ms+32).
// Phase 1 streams G straight from global (float4, 8-deep batches), no staging.
__global__ __launch_bounds__(512) void k_main(
    const float* __restrict__ x,  const float* __restrict__ W1,
    const float* __restrict__ b1, const float* __restrict__ W2,
    const float* __restrict__ b2, const float* __restrict__ W3,
    float* __restrict__ out)
{
    __shared__ float  sP[8 * 64 * 16];   // partials [ms][ts][16] = 32KB
    __shared__ float4 sAB[H];            // {A0, A1, B0, B1} per m (4KB)
    __shared__ float  sU0[H], sU1[H], sh[H];
    __shared__ float  sx[DD];
    __shared__ float  sgd[8];
    __shared__ float  sred[8 * 12];

    int tid = threadIdx.x;
    int ms = tid >> 6, ts = tid & 63;
    int wid = tid >> 5, lane = tid & 31;
    int n0 = 2 * blockIdx.x;

    // ---- phase 0: setup (threads 0-255) ----
    if (tid < DD) sx[tid] = x[tid];
    __syncthreads();

    float pL0 = 0.f, pL1 = 0.f, pY0 = 0.f, pY1 = 0.f;
    if (tid < H) {
        int m = tid;
        float z = b1[m], s = 0.f;
        const float4* wr = (const float4*)(W1 + m * DD);
#pragma unroll
        for (int i = 0; i < DD / 4; i++) {
            float4 w = __ldg(wr + i);
            float4 xv = *(const float4*)(sx + 4 * i);
            z += w.x * xv.x + w.y * xv.y + w.z * xv.z + w.w * xv.w;
            s += w.x * w.x + w.y * w.y + w.z * w.z + w.w * w.w;
        }
        float h = tanhf(z), w = 1.f - h * h;
        float h1 = w;
        float h2 = -2.f * h * w;
        float h3 = (4.f * h * h - 2.f * w) * w;
        float h4 = (16.f * w - 8.f * h * h) * h * w;
        float w20 = __ldg(&W2[n0 * H + m]);
        float w21 = __ldg(&W2[(n0 + 1) * H + m]);
        float A0 = w20 * h1, A1 = w21 * h1;
        float B0 = w20 * h2, B1 = w21 * h2;
        sAB[m] = make_float4(A0, A1, B0, B1);
        sU0[m] = w20 * h3 * s;
        sU1[m] = w21 * h3 * s;
        pL0 = B0 * s;  pL1 = B1 * s;
        pY0 = w20 * h4 * s * s;
        pY1 = w21 * h4 * s * s;
        sh[m] = h;
    }
    __syncthreads();

    // warps 0,1: a_n = W2[n].h + b2[n] -> g'..g'''' into sgd
    if (wid < 2) {
        int n = n0 + wid;
        float a = 0.f;
#pragma unroll
        for (int k = 0; k < 8; k++) {
            int m = lane + 32 * k;
            a += __ldg(&W2[n * H + m]) * sh[m];
        }
#pragma unroll
        for (int s = 16; s > 0; s >>= 1) a += __shfl_down_sync(0xFFFFFFFFu, a, s);
        if (lane == 0) {
            a += b2[n];
            float g = tanhf(a), gw = 1.f - g * g;
            sgd[wid * 4 + 0] = gw;
            sgd[wid * 4 + 1] = -2.f * g * gw;
            sgd[wid * 4 + 2] = (4.f * g * g - 2.f * gw) * gw;
            sgd[wid * 4 + 3] = (16.f * gw - 8.f * g * g) * g * gw;
        }
    }

    // ---- phase 1: stream G from global, 4 t-cols x 32 m per thread ----
    float M0[4] = {0,0,0,0}, M1[4] = {0,0,0,0};
    float P0[4] = {0,0,0,0}, P1[4] = {0,0,0,0};

    const float4* Gp = (const float4*)g_G + (32 * ms) * (H / 4) + ts;
    const float4* abp = sAB + 32 * ms;

#pragma unroll
    for (int b = 0; b < 4; b++) {
        float4 gv[8];
#pragma unroll
        for (int u = 0; u < 8; u++) gv[u] = __ldg(Gp + (8 * b + u) * (H / 4));
#pragma unroll
        for (int u = 0; u < 8; u++) {
            float4 ab = abp[8 * b + u];
            float4 g = gv[u];
            M0[0] += ab.x * g.x;  M0[1] += ab.x * g.y;  M0[2] += ab.x * g.z;  M0[3] += ab.x * g.w;
            M1[0] += ab.y * g.x;  M1[1] += ab.y * g.y;  M1[2] += ab.y * g.z;  M1[3] += ab.y * g.w;
            float gg0 = g.x * g.x, gg1 = g.y * g.y, gg2 = g.z * g.z, gg3 = g.w * g.w;
            P0[0] += ab.z * gg0;  P0[1] += ab.z * gg1;  P0[2] += ab.z * gg2;  P0[3] += ab.z * gg3;
            P1[0] += ab.w * gg0;  P1[1] += ab.w * gg1;  P1[2] += ab.w * gg2;  P1[3] += ab.w * gg3;
        }
    }

    {
        float4* sp = (float4*)(sP + (ms * 64 + ts) * 16);
        sp[0] = make_float4(M0[0], M0[1], M0[2], M0[3]);
        sp[1] = make_float4(M1[0], M1[1], M1[2], M1[3]);
        sp[2] = make_float4(P0[0], P0[1], P0[2], P0[3]);
        sp[3] = make_float4(P1[0], P1[1], P1[2], P1[3]);
    }
    __syncthreads();

    // ---- phase 2: combine partials + contraction (threads 0-255, t = tid) ----
    if (tid < H) {
        int tts = tid >> 2, c = tid & 3;
        float m0 = 0.f, m1 = 0.f, q0 = 0.f, q1 = 0.f;
#pragma unroll
        for (int w = 0; w < 8; w++) {
            const float* sp = sP + (w * 64 + tts) * 16;
            m0 += sp[c];
            m1 += sp[4 + c];
            q0 += sp[8 + c];
            q1 += sp[12 + c];
        }

        float4 ab = sAB[tid];
        float p[12];
        p[0]  = ab.x * m0;        p[1]  = ab.z * m0 * m0;  p[2]  = ab.z * q0;
        p[3]  = sU0[tid] * m0;    p[4]  = pL0;             p[5]  = pY0;
        p[6]  = ab.y * m1;        p[7]  = ab.w * m1 * m1;  p[8]  = ab.w * q1;
        p[9]  = sU1[tid] * m1;    p[10] = pL1;             p[11] = pY1;

#pragma unroll
        for (int k = 0; k < 12; k++) {
            float v = p[k];
#pragma unroll
            for (int s = 16; s > 0; s >>= 1) v += __shfl_down_sync(0xFFFFFFFFu, v, s);
            p[k] = v;
        }
        if (lane == 0) {
#pragma unroll
            for (int k = 0; k < 12; k++) sred[wid * 12 + k] = p[k];
        }
    }
    __syncthreads();

    if (tid == 0) {
        double dsum = 0.0;
#pragma unroll
        for (int nn = 0; nn < 2; nn++) {
            float Q = 0.f, R = 0.f, Z = 0.f, U = 0.f, L = 0.f, Y = 0.f;
#pragma unroll
            for (int w = 0; w < 8; w++) {
                Q += sred[w * 12 + nn * 6 + 0];
                R += sred[w * 12 + nn * 6 + 1];
                Z += sred[w * 12 + nn * 6 + 2];
                U += sred[w * 12 + nn * 6 + 3];
                L += sred[w * 12 + nn * 6 + 4];
                Y += sred[w * 12 + nn * 6 + 5];
            }
            float g1 = sgd[nn * 4 + 0], g2 = sgd[nn * 4 + 1];
            float g3 = sgd[nn * 4 + 2], g4 = sgd[nn * 4 + 3];
            float val = g4 * Q * Q
                      + g3 * (2.f * L * Q + 4.f * R)
                      + g2 * (L * L + 2.f * Z + 4.f * U)
                      + g1 * Y;
            dsum += (double)(__ldg(&W3[n0 + nn]) * val);
        }
        atomicAdd(&g_accum, dsum);
        __threadfence();
        unsigned int old = atomicAdd(&g_done, 1u);
        if (old == NB_MAIN - 1) {
            double r = atomicAdd(&g_accum, 0.0);
            out[0] = (float)r;
            g_accum = 0.0;
            g_done = 0u;
            __threadfence();
        }
    }
}

// ---------------- launch ----------------
extern "C" void kernel_launch(void* const* d_in, const int* in_sizes, int n_in,
                              void* d_out, int out_size) {
    const float* x  = (const float*)d_in[0];
    const float* W1 = (const float*)d_in[1];
    const float* b1 = (const float*)d_in[2];
    const float* W2 = (const float*)d_in[3];
    const float* b2 = (const float*)d_in[4];
    const float* W3 = (const float*)d_in[5];
    // d_in[6] = b3: does not affect the 4th derivative
    float* out = (float*)d_out;

    k_pre<<<NB_MAIN, 256>>>(W1);
    k_main<<<NB_MAIN, 512>>>(x, W1, b1, W2, b2, W3, out);
}